// round 11
// baseline (speedup 1.0000x reference)
#include <cuda_runtime.h>
#include <cuda_fp16.h>
#include <cstdint>
#include <math.h>

#define NR 8192
#define ND 1024
#define BM 128
#define BKD 32

// tile offsets within a stage (each [rows][32] fp16 tile: rows*64 bytes)
#define T_AHI 0
#define T_ALO 8192
#define T_BHI 16384
#define T_BLO 24576

// scratch
__device__ __half g_xh[(size_t)NR * ND], g_xl[(size_t)NR * ND];
__device__ __half g_Wh[(size_t)ND * ND], g_Wl[(size_t)ND * ND];
__device__ __half g_hh[(size_t)NR * ND], g_hl[(size_t)NR * ND];
__device__ __half g_hT[(size_t)ND * NR];
__device__ __half g_Pf[(size_t)NR * NR];
__device__ float g_rowsum[NR];

// ------------------------------------------------------------------ helpers
__device__ __forceinline__ uint32_t smem_u32(const void* p) {
    uint32_t a;
    asm("{ .reg .u64 t; cvta.to.shared.u64 t, %1; cvt.u32.u64 %0, t; }" : "=r"(a) : "l"(p));
    return a;
}
__device__ __forceinline__ void cp16(uint32_t s, const __half* g) {
    asm volatile("cp.async.cg.shared.global [%0], [%1], 16;"
                 :: "r"(s), "l"(__cvta_generic_to_global((const void*)g)) : "memory");
}
__device__ __forceinline__ void cp_commit() {
    asm volatile("cp.async.commit_group;" ::: "memory");
}
template <int N> __device__ __forceinline__ void cp_wait() {
    asm volatile("cp.async.wait_group %0;" :: "n"(N) : "memory");
}
__device__ __forceinline__ void ldsm4(uint32_t* r, uint32_t a) {
    asm volatile("ldmatrix.sync.aligned.m8n8.x4.shared.b16 {%0,%1,%2,%3}, [%4];"
                 : "=r"(r[0]), "=r"(r[1]), "=r"(r[2]), "=r"(r[3]) : "r"(a));
}
__device__ __forceinline__ void mma16816(float* c, const uint32_t* a, uint32_t b0, uint32_t b1) {
    asm volatile(
        "mma.sync.aligned.m16n8k16.row.col.f32.f16.f16.f32 "
        "{%0,%1,%2,%3},{%4,%5,%6,%7},{%8,%9},{%0,%1,%2,%3};"
        : "+f"(c[0]), "+f"(c[1]), "+f"(c[2]), "+f"(c[3])
        : "r"(a[0]), "r"(a[1]), "r"(a[2]), "r"(a[3]), "r"(b0), "r"(b1));
}
__device__ __forceinline__ float ftanh(float x) {
    float y; asm("tanh.approx.f32 %0, %1;" : "=f"(y) : "f"(x)); return y;
}
__device__ __forceinline__ void split16(float v, __half& h, __half& l) {
    h = __float2half_rn(v);
    l = __float2half_rn(v - __half2float(h));
}
// swizzled smem byte offset for (row, 16B-chunk) within a [rows][32] fp16 tile
__device__ __forceinline__ uint32_t swz(int row, int c) {
    return (uint32_t)(row * 64 + ((c ^ ((row >> 1) & 3)) << 4));
}

// load a [ITERS*THR/4 rows][32] fp16 tile
template <int THR, int ITERS>
__device__ __forceinline__ void load_tileT(const __half* __restrict__ base, size_t ld,
                                           int k0, uint32_t st, int tid) {
    #pragma unroll
    for (int i = 0; i < ITERS; i++) {
        int idx = tid + i * THR;
        int row = idx >> 2, c = idx & 3;
        cp16(st + swz(row, c), base + (size_t)row * ld + k0 + c * 8);
    }
}

// ------------------------------------------------------- GEMM (0=K1,1=K2,2=K3)
// MODE 1 computes only by<=bx blocks; mirrors P and accumulates row+col sums
// (tanh bounds scores, so exp needs no max subtraction).
// MODE<2 mainloop: fragment software pipeline across the 6 (product,ks) phases
// so each 16-HMMA block issues while the next phase's LDSMs are in flight.
template <int MODE>
__global__ __launch_bounds__((MODE == 2) ? 512 : 256, 1)
void gemm_tc(const float* __restrict__ bias, float* __restrict__ out)
{
    constexpr int THR   = (MODE == 2) ? 512 : 256;
    constexpr int S     = (MODE == 2) ? 4 : 3;
    constexpr int STAGE = (MODE < 2) ? 32768 : 24576;   // both: 98304 total
    constexpr int BNx   = (MODE == 2) ? 256 : 128;
    constexpr int K     = (MODE == 2) ? NR : ND;
    constexpr int NC    = K / BKD;

    extern __shared__ char smem[];
    const uint32_t sb = smem_u32(smem);
    const int tid = threadIdx.x, lane = tid & 31, wid = tid >> 5;
    const int bx = blockIdx.x, by = blockIdx.y;
    if (MODE == 1 && by > bx) return;   // symmetry (uniform whole-CTA exit)
    const int mo = (wid & 3) * 32, no = (wid >> 2) * 64;

    const __half *Ahi, *Alo, *Bhi, *Blo;
    size_t lda, ldb;
    if (MODE == 0) {
        Ahi = g_xh + (size_t)by * BM * ND; Alo = g_xl + (size_t)by * BM * ND;
        Bhi = g_Wh + (size_t)bx * BNx * ND; Blo = g_Wl + (size_t)bx * BNx * ND;
        lda = ND; ldb = ND;
    } else if (MODE == 1) {
        Ahi = g_hh + (size_t)by * BM * ND; Alo = g_hl + (size_t)by * BM * ND;
        Bhi = g_hh + (size_t)bx * BNx * ND; Blo = g_hl + (size_t)bx * BNx * ND;
        lda = ND; ldb = ND;
    } else {
        Ahi = g_Pf + (size_t)by * BM * NR; Alo = nullptr;
        Bhi = g_hT + (size_t)bx * BNx * NR; Blo = nullptr;
        lda = NR; ldb = NR;
    }

    auto load_chunk = [&](int k0, uint32_t st) {
        if (MODE < 2) {
            load_tileT<THR, 2>(Ahi, lda, k0, st + T_AHI, tid);
            load_tileT<THR, 2>(Alo, lda, k0, st + T_ALO, tid);
            load_tileT<THR, 2>(Bhi, ldb, k0, st + T_BHI, tid);
            load_tileT<THR, 2>(Blo, ldb, k0, st + T_BLO, tid);
        } else {
            load_tileT<THR, 1>(Ahi, lda, k0, st + 0, tid);      // 128x32
            load_tileT<THR, 2>(Bhi, ldb, k0, st + 8192, tid);   // 256x32
        }
    };

    float c[2][8][4] = {};

    // fragment loaders (warp-level)
    auto ldA = [&](uint32_t (*dst)[4], uint32_t base, int ks) {
        #pragma unroll
        for (int mf = 0; mf < 2; mf++) {
            int row = mo + mf * 16 + (lane & 15);
            int ch = 2 * ks + (lane >> 4);
            ldsm4(dst[mf], base + swz(row, ch));
        }
    };
    auto ldB = [&](uint32_t (*dst)[4], uint32_t base, int ks) {
        #pragma unroll
        for (int np = 0; np < 4; np++) {
            int row = no + np * 16 + (lane & 7) + ((lane >> 4) << 3);
            int ch = 2 * ks + ((lane >> 3) & 1);
            ldsm4(dst[np], base + swz(row, ch));
        }
    };
    auto mmaAll = [&](uint32_t (*A)[4], uint32_t (*B)[4]) {
        #pragma unroll
        for (int mf = 0; mf < 2; mf++)
            #pragma unroll
            for (int nf = 0; nf < 8; nf++)
                mma16816(c[mf][nf], A[mf],
                         B[nf >> 1][(nf & 1) * 2], B[nf >> 1][(nf & 1) * 2 + 1]);
    };

    // prologue: chunks 0..S-2
    #pragma unroll
    for (int s = 0; s < S - 1; s++) {
        load_chunk(s * BKD, sb + s * STAGE);
        cp_commit();
    }

    for (int i = 0; i < NC; i++) {
        cp_wait<S - 2>();
        __syncthreads();

        if (i + S - 1 < NC)
            load_chunk((i + S - 1) * BKD, sb + ((i + S - 1) % S) * STAGE);
        cp_commit();

        const uint32_t st = sb + (i % S) * STAGE;
        if (MODE < 2) {
            // phase-pipelined 3-limb products, ks = 0 then 1
            uint32_t A0[2][4], A1[2][4], B0[4][4], B1[4][4], B2[4][4];
            ldA(A0, st + T_AHI, 0);
            ldB(B0, st + T_BHI, 0);
            ldB(B1, st + T_BLO, 0);          // prefetch blo(0)
            mmaAll(A0, B0);                  // ahi*bhi   ks0
            ldA(A1, st + T_ALO, 0);          // prefetch alo(0)
            mmaAll(A0, B1);                  // ahi*blo   ks0
            ldA(A0, st + T_AHI, 1);          // prefetch ahi(1)  (A0 dead)
            ldB(B2, st + T_BHI, 1);          // prefetch bhi(1)
            mmaAll(A1, B0);                  // alo*bhi   ks0
            ldB(B1, st + T_BLO, 1);          // prefetch blo(1)
            mmaAll(A0, B2);                  // ahi*bhi   ks1
            ldA(A1, st + T_ALO, 1);          // prefetch alo(1)
            mmaAll(A0, B1);                  // ahi*blo   ks1
            mmaAll(A1, B2);                  // alo*bhi   ks1
        } else {
            #pragma unroll
            for (int ks = 0; ks < 2; ks++) {
                uint32_t a[2][4], b[4][4];
                ldA(a, st, ks);
                ldB(b, st + 8192, ks);
                mmaAll(a, b);
            }
        }
    }
    __syncthreads();   // all compute smem reads done (epilogue aliases stages)

    // --------------------------------------------------------- epilogue
    __half* sp = (__half*)smem;            // [128][132] staging (aliases stages)
    const bool mirror = (MODE == 1) && (bx != by);
    float rs[2][2] = {};
    #pragma unroll
    for (int mf = 0; mf < 2; mf++) {
        const int rl0 = mo + mf * 16 + (lane >> 2);
        const int rl1 = rl0 + 8;
        const int r0 = by * BM + rl0, r1 = by * BM + rl1;
        float inv0 = 0.f, inv1 = 0.f;
        if (MODE == 2) {
            inv0 = 1.0f / __ldg(&g_rowsum[r0]);
            inv1 = 1.0f / __ldg(&g_rowsum[r1]);
        }
        #pragma unroll
        for (int nf = 0; nf < 8; nf++) {
            const int cl = no + nf * 8 + 2 * (lane & 3);
            const int col = bx * BNx + cl;
            float v0 = c[mf][nf][0], v1 = c[mf][nf][1];
            float v2 = c[mf][nf][2], v3 = c[mf][nf][3];
            if (MODE == 0) {
                float b0 = __ldg(&bias[col]), b1 = __ldg(&bias[col + 1]);
                v0 += b0; v1 += b1; v2 += b0; v3 += b1;
                __half h0, l0, h1, l1, h2, l2, h3, l3;
                split16(v0, h0, l0); split16(v1, h1, l1);
                split16(v2, h2, l2); split16(v3, h3, l3);
                *(__half2*)(g_hh + (size_t)r0 * ND + col) = __halves2half2(h0, h1);
                *(__half2*)(g_hl + (size_t)r0 * ND + col) = __halves2half2(l0, l1);
                *(__half2*)(g_hh + (size_t)r1 * ND + col) = __halves2half2(h2, h3);
                *(__half2*)(g_hl + (size_t)r1 * ND + col) = __halves2half2(l2, l3);
            } else if (MODE == 1) {
                float p0 = __expf(ftanh(v0)), p1 = __expf(ftanh(v1));
                float p2 = __expf(ftanh(v2)), p3 = __expf(ftanh(v3));
                rs[mf][0] += p0 + p1; rs[mf][1] += p2 + p3;
                __half2 q0 = __halves2half2(__float2half_rn(p0), __float2half_rn(p1));
                __half2 q1 = __halves2half2(__float2half_rn(p2), __float2half_rn(p3));
                *(__half2*)(g_Pf + (size_t)r0 * NR + col) = q0;
                *(__half2*)(g_Pf + (size_t)r1 * NR + col) = q1;
                if (mirror) {
                    *(__half2*)(sp + rl0 * 132 + cl) = q0;
                    *(__half2*)(sp + rl1 * 132 + cl) = q1;
                }
            } else {
                float2 o0 = make_float2(tanhf(v0 * inv0), tanhf(v1 * inv0));
                float2 o1 = make_float2(tanhf(v2 * inv1), tanhf(v3 * inv1));
                *(float2*)(out + (size_t)r0 * ND + col) = o0;
                *(float2*)(out + (size_t)r1 * ND + col) = o1;
            }
        }
    }
    if (MODE == 1) {
        #pragma unroll
        for (int mf = 0; mf < 2; mf++)
            #pragma unroll
            for (int hh = 0; hh < 2; hh++) {
                float v = rs[mf][hh];
                v += __shfl_xor_sync(0xffffffffu, v, 1);
                v += __shfl_xor_sync(0xffffffffu, v, 2);
                if ((lane & 3) == 0) {
                    int r = by * BM + mo + mf * 16 + (lane >> 2) + hh * 8;
                    atomicAdd(&g_rowsum[r], v);
                }
            }
        if (mirror) {
            __syncthreads();
            // mirror block: write P[bx-range][by-range] coalesced + column sums
            const int cc = tid >> 1;            // local col 0..127
            const int rh = (tid & 1) * 64;      // row half
            float csum = 0.0f;
            #pragma unroll
            for (int q = 0; q < 8; q++) {
                __half tmp[8];
                #pragma unroll
                for (int r = 0; r < 8; r++) {
                    __half v = sp[(rh + q * 8 + r) * 132 + cc];
                    tmp[r] = v;
                    csum += __half2float(v);
                }
                *(uint4*)(g_Pf + (size_t)(bx * BNx + cc) * NR + by * BM + rh + q * 8) =
                    *(uint4*)tmp;
            }
            float o = __shfl_down_sync(0xffffffffu, csum, 1);
            if ((lane & 1) == 0) atomicAdd(&g_rowsum[bx * BNx + cc], csum + o);
        }
    }
}

// ------------------------------------------------------------- small kernels
__global__ void k_split(const float* __restrict__ src, __half* __restrict__ hi,
                        __half* __restrict__ lo, int n4)
{
    int i = blockIdx.x * blockDim.x + threadIdx.x;
    if (i >= n4) return;
    float4 v = ((const float4*)src)[i];
    __half h[4], l[4];
    split16(v.x, h[0], l[0]); split16(v.y, h[1], l[1]);
    split16(v.z, h[2], l[2]); split16(v.w, h[3], l[3]);
    ((uint2*)hi)[i] = *(uint2*)h;
    ((uint2*)lo)[i] = *(uint2*)l;
}
__global__ void k_zero_rowsum()
{
    int i = blockIdx.x * blockDim.x + threadIdx.x;
    if (i < NR) g_rowsum[i] = 0.0f;
}
// tiled transpose: g_hT[c][r] = g_hh[r][c]
__global__ void k_transpose()
{
    __shared__ __half t[32][33];
    int x = threadIdx.x, y = threadIdx.y;           // 32 x 8
    int r0 = blockIdx.y * 32, c0 = blockIdx.x * 32;
    #pragma unroll
    for (int i = 0; i < 32; i += 8)
        t[y + i][x] = g_hh[(size_t)(r0 + y + i) * ND + c0 + x];
    __syncthreads();
    #pragma unroll
    for (int i = 0; i < 32; i += 8)
        g_hT[(size_t)(c0 + y + i) * NR + r0 + x] = t[x][y + i];
}

// ------------------------------------------------------------------ launcher
extern "C" void kernel_launch(void* const* d_in, const int* in_sizes, int n_in,
                              void* d_out, int out_size)
{
    const float* x = (const float*)d_in[0];
    const float* W = (const float*)d_in[1];
    const float* b = (const float*)d_in[2];
    float* out = (float*)d_out;

    cudaFuncSetAttribute(gemm_tc<0>, cudaFuncAttributeMaxDynamicSharedMemorySize, 98304);
    cudaFuncSetAttribute(gemm_tc<1>, cudaFuncAttributeMaxDynamicSharedMemorySize, 98304);
    cudaFuncSetAttribute(gemm_tc<2>, cudaFuncAttributeMaxDynamicSharedMemorySize, 98304);

    __half *xh, *xl, *wh, *wl;
    cudaGetSymbolAddress((void**)&xh, g_xh); cudaGetSymbolAddress((void**)&xl, g_xl);
    cudaGetSymbolAddress((void**)&wh, g_Wh); cudaGetSymbolAddress((void**)&wl, g_Wl);

    int nx4 = NR * ND / 4, nw4 = ND * ND / 4;
    k_split<<<(nx4 + 255) / 256, 256>>>(x, xh, xl, nx4);
    k_split<<<(nw4 + 255) / 256, 256>>>(W, wh, wl, nw4);
    k_zero_rowsum<<<NR / 256, 256>>>();

    gemm_tc<0><<<dim3(ND / 128, NR / BM), 256, 98304>>>(b, nullptr);
    k_transpose<<<dim3(ND / 32, NR / 32), dim3(32, 8)>>>();
    gemm_tc<1><<<dim3(NR / 128, NR / BM), 256, 98304>>>(nullptr, nullptr);
    gemm_tc<2><<<dim3(ND / 256, NR / BM), 512, 98304>>>(nullptr, out);
}

// round 12
// speedup vs baseline: 1.2876x; 1.2876x over previous
#include <cuda_runtime.h>
#include <cuda_fp16.h>
#include <cstdint>
#include <math.h>

#define NR 8192
#define ND 1024
#define BM 128
#define BKD 32

// tile offsets within a stage (each [rows][32] fp16 tile: rows*64 bytes)
#define T_AHI 0
#define T_ALO 8192
#define T_BHI 16384
#define T_BLO 24576

// scratch
__device__ __half g_xh[(size_t)NR * ND], g_xl[(size_t)NR * ND];
__device__ __half g_Wh[(size_t)ND * ND], g_Wl[(size_t)ND * ND];
__device__ __half g_hh[(size_t)NR * ND], g_hl[(size_t)NR * ND];
__device__ __half g_hT[(size_t)ND * NR];
__device__ __half g_Pf[(size_t)NR * NR];
__device__ float g_rowsum[NR];

// ------------------------------------------------------------------ helpers
__device__ __forceinline__ uint32_t smem_u32(const void* p) {
    uint32_t a;
    asm("{ .reg .u64 t; cvta.to.shared.u64 t, %1; cvt.u32.u64 %0, t; }" : "=r"(a) : "l"(p));
    return a;
}
__device__ __forceinline__ void cp16(uint32_t s, const __half* g) {
    asm volatile("cp.async.cg.shared.global [%0], [%1], 16;"
                 :: "r"(s), "l"(__cvta_generic_to_global((const void*)g)) : "memory");
}
__device__ __forceinline__ void cp_commit() {
    asm volatile("cp.async.commit_group;" ::: "memory");
}
template <int N> __device__ __forceinline__ void cp_wait() {
    asm volatile("cp.async.wait_group %0;" :: "n"(N) : "memory");
}
__device__ __forceinline__ void ldsm4(uint32_t* r, uint32_t a) {
    asm volatile("ldmatrix.sync.aligned.m8n8.x4.shared.b16 {%0,%1,%2,%3}, [%4];"
                 : "=r"(r[0]), "=r"(r[1]), "=r"(r[2]), "=r"(r[3]) : "r"(a));
}
__device__ __forceinline__ void mma16816(float* c, const uint32_t* a, uint32_t b0, uint32_t b1) {
    asm volatile(
        "mma.sync.aligned.m16n8k16.row.col.f32.f16.f16.f32 "
        "{%0,%1,%2,%3},{%4,%5,%6,%7},{%8,%9},{%0,%1,%2,%3};"
        : "+f"(c[0]), "+f"(c[1]), "+f"(c[2]), "+f"(c[3])
        : "r"(a[0]), "r"(a[1]), "r"(a[2]), "r"(a[3]), "r"(b0), "r"(b1));
}
__device__ __forceinline__ float ftanh(float x) {
    float y; asm("tanh.approx.f32 %0, %1;" : "=f"(y) : "f"(x)); return y;
}
__device__ __forceinline__ void split16(float v, __half& h, __half& l) {
    h = __float2half_rn(v);
    l = __float2half_rn(v - __half2float(h));
}
// swizzled smem byte offset for (row, 16B-chunk) within a [rows][32] fp16 tile
__device__ __forceinline__ uint32_t swz(int row, int c) {
    return (uint32_t)(row * 64 + ((c ^ ((row >> 1) & 3)) << 4));
}

// load a [ITERS*THR/4 rows][32] fp16 tile
template <int THR, int ITERS>
__device__ __forceinline__ void load_tileT(const __half* __restrict__ base, size_t ld,
                                           int k0, uint32_t st, int tid) {
    #pragma unroll
    for (int i = 0; i < ITERS; i++) {
        int idx = tid + i * THR;
        int row = idx >> 2, c = idx & 3;
        cp16(st + swz(row, c), base + (size_t)row * ld + k0 + c * 8);
    }
}

// ------------------------------------------------------- GEMM (0=K1,1=K2,2=K3)
// MODE 0: 3 limb products (ahi*bhi + ahi*blo + alo*bhi) — full accuracy for h.
// MODE 1: 2 limb products (ahi*bhi + alo*bhi) = h_full * h_hi. Scores feed
//         tanh (saturating) + softmax-average, so the dropped cross term's
//         ~1.5e-3 score error lands ~3e-4 in the output. by<=bx blocks only;
//         mirrors P + accumulates row & col sums (tanh bounds scores: no max).
// MODE 2: single product (P @ h).
template <int MODE>
__global__ __launch_bounds__((MODE == 2) ? 512 : 256, (MODE == 2) ? 1 : 2)
void gemm_tc(const float* __restrict__ bias, float* __restrict__ out)
{
    constexpr int THR   = (MODE == 2) ? 512 : 256;
    constexpr int S     = (MODE == 2) ? 4 : 3;
    constexpr int STAGE = (MODE < 2) ? 32768 : 24576;   // both: 98304 total
    constexpr int BNx   = (MODE == 2) ? 256 : 128;
    constexpr int K     = (MODE == 2) ? NR : ND;
    constexpr int NC    = K / BKD;

    extern __shared__ char smem[];
    const uint32_t sb = smem_u32(smem);
    const int tid = threadIdx.x, lane = tid & 31, wid = tid >> 5;
    const int bx = blockIdx.x, by = blockIdx.y;
    if (MODE == 1 && by > bx) return;   // symmetry (uniform whole-CTA exit)
    const int mo = (wid & 3) * 32, no = (wid >> 2) * 64;

    const __half *Ahi, *Alo, *Bhi, *Blo;
    size_t lda, ldb;
    if (MODE == 0) {
        Ahi = g_xh + (size_t)by * BM * ND; Alo = g_xl + (size_t)by * BM * ND;
        Bhi = g_Wh + (size_t)bx * BNx * ND; Blo = g_Wl + (size_t)bx * BNx * ND;
        lda = ND; ldb = ND;
    } else if (MODE == 1) {
        Ahi = g_hh + (size_t)by * BM * ND; Alo = g_hl + (size_t)by * BM * ND;
        Bhi = g_hh + (size_t)bx * BNx * ND; Blo = nullptr;
        lda = ND; ldb = ND;
    } else {
        Ahi = g_Pf + (size_t)by * BM * NR; Alo = nullptr;
        Bhi = g_hT + (size_t)bx * BNx * NR; Blo = nullptr;
        lda = NR; ldb = NR;
    }

    auto load_chunk = [&](int k0, uint32_t st) {
        if (MODE == 0) {
            load_tileT<THR, 2>(Ahi, lda, k0, st + T_AHI, tid);
            load_tileT<THR, 2>(Alo, lda, k0, st + T_ALO, tid);
            load_tileT<THR, 2>(Bhi, ldb, k0, st + T_BHI, tid);
            load_tileT<THR, 2>(Blo, ldb, k0, st + T_BLO, tid);
        } else if (MODE == 1) {
            load_tileT<THR, 2>(Ahi, lda, k0, st + T_AHI, tid);
            load_tileT<THR, 2>(Alo, lda, k0, st + T_ALO, tid);
            load_tileT<THR, 2>(Bhi, ldb, k0, st + T_BHI, tid);
        } else {
            load_tileT<THR, 1>(Ahi, lda, k0, st + 0, tid);      // 128x32
            load_tileT<THR, 2>(Bhi, ldb, k0, st + 8192, tid);   // 256x32
        }
    };

    float c[2][8][4] = {};

    // prologue: chunks 0..S-2
    #pragma unroll
    for (int s = 0; s < S - 1; s++) {
        load_chunk(s * BKD, sb + s * STAGE);
        cp_commit();
    }

    for (int i = 0; i < NC; i++) {
        cp_wait<S - 2>();
        __syncthreads();

        if (i + S - 1 < NC)
            load_chunk((i + S - 1) * BKD, sb + ((i + S - 1) % S) * STAGE);
        cp_commit();

        const uint32_t st = sb + (i % S) * STAGE;
        #pragma unroll
        for (int ks = 0; ks < 2; ks++) {
            if (MODE == 0) {
                uint32_t ahi[2][4], bhi[4][4], tmp[4][4];
                #pragma unroll
                for (int mf = 0; mf < 2; mf++) {
                    int row = mo + mf * 16 + (lane & 15);
                    int ch = 2 * ks + (lane >> 4);
                    ldsm4(ahi[mf], st + T_AHI + swz(row, ch));
                }
                #pragma unroll
                for (int np = 0; np < 4; np++) {
                    int row = no + np * 16 + (lane & 7) + ((lane >> 4) << 3);
                    int ch = 2 * ks + ((lane >> 3) & 1);
                    ldsm4(bhi[np], st + T_BHI + swz(row, ch));
                }
                #pragma unroll
                for (int mf = 0; mf < 2; mf++)
                    #pragma unroll
                    for (int nf = 0; nf < 8; nf++)
                        mma16816(c[mf][nf], ahi[mf],
                                 bhi[nf >> 1][(nf & 1) * 2], bhi[nf >> 1][(nf & 1) * 2 + 1]);
                #pragma unroll
                for (int np = 0; np < 4; np++) {
                    int row = no + np * 16 + (lane & 7) + ((lane >> 4) << 3);
                    int ch = 2 * ks + ((lane >> 3) & 1);
                    ldsm4(tmp[np], st + T_BLO + swz(row, ch));
                }
                #pragma unroll
                for (int mf = 0; mf < 2; mf++)
                    #pragma unroll
                    for (int nf = 0; nf < 8; nf++)
                        mma16816(c[mf][nf], ahi[mf],
                                 tmp[nf >> 1][(nf & 1) * 2], tmp[nf >> 1][(nf & 1) * 2 + 1]);
                #pragma unroll
                for (int mf = 0; mf < 2; mf++) {
                    int row = mo + mf * 16 + (lane & 15);
                    int ch = 2 * ks + (lane >> 4);
                    ldsm4(tmp[mf], st + T_ALO + swz(row, ch));
                }
                #pragma unroll
                for (int mf = 0; mf < 2; mf++)
                    #pragma unroll
                    for (int nf = 0; nf < 8; nf++)
                        mma16816(c[mf][nf], tmp[mf],
                                 bhi[nf >> 1][(nf & 1) * 2], bhi[nf >> 1][(nf & 1) * 2 + 1]);
            } else if (MODE == 1) {
                uint32_t ahi[2][4], bhi[4][4], alo[2][4];
                #pragma unroll
                for (int mf = 0; mf < 2; mf++) {
                    int row = mo + mf * 16 + (lane & 15);
                    int ch = 2 * ks + (lane >> 4);
                    ldsm4(ahi[mf], st + T_AHI + swz(row, ch));
                }
                #pragma unroll
                for (int np = 0; np < 4; np++) {
                    int row = no + np * 16 + (lane & 7) + ((lane >> 4) << 3);
                    int ch = 2 * ks + ((lane >> 3) & 1);
                    ldsm4(bhi[np], st + T_BHI + swz(row, ch));
                }
                #pragma unroll
                for (int mf = 0; mf < 2; mf++)
                    #pragma unroll
                    for (int nf = 0; nf < 8; nf++)
                        mma16816(c[mf][nf], ahi[mf],
                                 bhi[nf >> 1][(nf & 1) * 2], bhi[nf >> 1][(nf & 1) * 2 + 1]);
                #pragma unroll
                for (int mf = 0; mf < 2; mf++) {
                    int row = mo + mf * 16 + (lane & 15);
                    int ch = 2 * ks + (lane >> 4);
                    ldsm4(alo[mf], st + T_ALO + swz(row, ch));
                }
                #pragma unroll
                for (int mf = 0; mf < 2; mf++)
                    #pragma unroll
                    for (int nf = 0; nf < 8; nf++)
                        mma16816(c[mf][nf], alo[mf],
                                 bhi[nf >> 1][(nf & 1) * 2], bhi[nf >> 1][(nf & 1) * 2 + 1]);
            } else {
                uint32_t a[2][4], b[4][4];
                #pragma unroll
                for (int mf = 0; mf < 2; mf++) {
                    int row = mo + mf * 16 + (lane & 15);
                    int ch = 2 * ks + (lane >> 4);
                    ldsm4(a[mf], st + swz(row, ch));
                }
                #pragma unroll
                for (int np = 0; np < 4; np++) {
                    int row = no + np * 16 + (lane & 7) + ((lane >> 4) << 3);
                    int ch = 2 * ks + ((lane >> 3) & 1);
                    ldsm4(b[np], st + 8192 + swz(row, ch));
                }
                #pragma unroll
                for (int mf = 0; mf < 2; mf++)
                    #pragma unroll
                    for (int nf = 0; nf < 8; nf++)
                        mma16816(c[mf][nf], a[mf],
                                 b[nf >> 1][(nf & 1) * 2], b[nf >> 1][(nf & 1) * 2 + 1]);
            }
        }
    }
    __syncthreads();   // all compute smem reads done (epilogue aliases stages)

    // --------------------------------------------------------- epilogue
    __half* sp = (__half*)smem;            // [128][132] staging (aliases stages)
    const bool mirror = (MODE == 1) && (bx != by);
    float rs[2][2] = {};
    #pragma unroll
    for (int mf = 0; mf < 2; mf++) {
        const int rl0 = mo + mf * 16 + (lane >> 2);
        const int rl1 = rl0 + 8;
        const int r0 = by * BM + rl0, r1 = by * BM + rl1;
        float inv0 = 0.f, inv1 = 0.f;
        if (MODE == 2) {
            inv0 = 1.0f / __ldg(&g_rowsum[r0]);
            inv1 = 1.0f / __ldg(&g_rowsum[r1]);
        }
        #pragma unroll
        for (int nf = 0; nf < 8; nf++) {
            const int cl = no + nf * 8 + 2 * (lane & 3);
            const int col = bx * BNx + cl;
            float v0 = c[mf][nf][0], v1 = c[mf][nf][1];
            float v2 = c[mf][nf][2], v3 = c[mf][nf][3];
            if (MODE == 0) {
                float b0 = __ldg(&bias[col]), b1 = __ldg(&bias[col + 1]);
                v0 += b0; v1 += b1; v2 += b0; v3 += b1;
                __half h0, l0, h1, l1, h2, l2, h3, l3;
                split16(v0, h0, l0); split16(v1, h1, l1);
                split16(v2, h2, l2); split16(v3, h3, l3);
                *(__half2*)(g_hh + (size_t)r0 * ND + col) = __halves2half2(h0, h1);
                *(__half2*)(g_hl + (size_t)r0 * ND + col) = __halves2half2(l0, l1);
                *(__half2*)(g_hh + (size_t)r1 * ND + col) = __halves2half2(h2, h3);
                *(__half2*)(g_hl + (size_t)r1 * ND + col) = __halves2half2(l2, l3);
            } else if (MODE == 1) {
                float p0 = __expf(ftanh(v0)), p1 = __expf(ftanh(v1));
                float p2 = __expf(ftanh(v2)), p3 = __expf(ftanh(v3));
                rs[mf][0] += p0 + p1; rs[mf][1] += p2 + p3;
                __half2 q0 = __halves2half2(__float2half_rn(p0), __float2half_rn(p1));
                __half2 q1 = __halves2half2(__float2half_rn(p2), __float2half_rn(p3));
                *(__half2*)(g_Pf + (size_t)r0 * NR + col) = q0;
                *(__half2*)(g_Pf + (size_t)r1 * NR + col) = q1;
                if (mirror) {
                    *(__half2*)(sp + rl0 * 132 + cl) = q0;
                    *(__half2*)(sp + rl1 * 132 + cl) = q1;
                }
            } else {
                float2 o0 = make_float2(tanhf(v0 * inv0), tanhf(v1 * inv0));
                float2 o1 = make_float2(tanhf(v2 * inv1), tanhf(v3 * inv1));
                *(float2*)(out + (size_t)r0 * ND + col) = o0;
                *(float2*)(out + (size_t)r1 * ND + col) = o1;
            }
        }
    }
    if (MODE == 1) {
        #pragma unroll
        for (int mf = 0; mf < 2; mf++)
            #pragma unroll
            for (int hh = 0; hh < 2; hh++) {
                float v = rs[mf][hh];
                v += __shfl_xor_sync(0xffffffffu, v, 1);
                v += __shfl_xor_sync(0xffffffffu, v, 2);
                if ((lane & 3) == 0) {
                    int r = by * BM + mo + mf * 16 + (lane >> 2) + hh * 8;
                    atomicAdd(&g_rowsum[r], v);
                }
            }
        if (mirror) {
            __syncthreads();
            // mirror block: write P[bx-range][by-range] coalesced + column sums
            const int cc = tid >> 1;            // local col 0..127
            const int rh = (tid & 1) * 64;      // row half
            float csum = 0.0f;
            #pragma unroll
            for (int q = 0; q < 8; q++) {
                __half tmp[8];
                #pragma unroll
                for (int r = 0; r < 8; r++) {
                    __half v = sp[(rh + q * 8 + r) * 132 + cc];
                    tmp[r] = v;
                    csum += __half2float(v);
                }
                *(uint4*)(g_Pf + (size_t)(bx * BNx + cc) * NR + by * BM + rh + q * 8) =
                    *(uint4*)tmp;
            }
            float o = __shfl_down_sync(0xffffffffu, csum, 1);
            if ((lane & 1) == 0) atomicAdd(&g_rowsum[bx * BNx + cc], csum + o);
        }
    }
}

// ------------------------------------------------------------- small kernels
__global__ void k_split(const float* __restrict__ src, __half* __restrict__ hi,
                        __half* __restrict__ lo, int n4)
{
    int i = blockIdx.x * blockDim.x + threadIdx.x;
    if (i >= n4) return;
    float4 v = ((const float4*)src)[i];
    __half h[4], l[4];
    split16(v.x, h[0], l[0]); split16(v.y, h[1], l[1]);
    split16(v.z, h[2], l[2]); split16(v.w, h[3], l[3]);
    ((uint2*)hi)[i] = *(uint2*)h;
    ((uint2*)lo)[i] = *(uint2*)l;
}
__global__ void k_zero_rowsum()
{
    int i = blockIdx.x * blockDim.x + threadIdx.x;
    if (i < NR) g_rowsum[i] = 0.0f;
}
// tiled transpose: g_hT[c][r] = g_hh[r][c]
__global__ void k_transpose()
{
    __shared__ __half t[32][33];
    int x = threadIdx.x, y = threadIdx.y;           // 32 x 8
    int r0 = blockIdx.y * 32, c0 = blockIdx.x * 32;
    #pragma unroll
    for (int i = 0; i < 32; i += 8)
        t[y + i][x] = g_hh[(size_t)(r0 + y + i) * ND + c0 + x];
    __syncthreads();
    #pragma unroll
    for (int i = 0; i < 32; i += 8)
        g_hT[(size_t)(c0 + y + i) * NR + r0 + x] = t[x][y + i];
}

// ------------------------------------------------------------------ launcher
extern "C" void kernel_launch(void* const* d_in, const int* in_sizes, int n_in,
                              void* d_out, int out_size)
{
    const float* x = (const float*)d_in[0];
    const float* W = (const float*)d_in[1];
    const float* b = (const float*)d_in[2];
    float* out = (float*)d_out;

    cudaFuncSetAttribute(gemm_tc<0>, cudaFuncAttributeMaxDynamicSharedMemorySize, 98304);
    cudaFuncSetAttribute(gemm_tc<1>, cudaFuncAttributeMaxDynamicSharedMemorySize, 98304);
    cudaFuncSetAttribute(gemm_tc<2>, cudaFuncAttributeMaxDynamicSharedMemorySize, 98304);

    __half *xh, *xl, *wh, *wl;
    cudaGetSymbolAddress((void**)&xh, g_xh); cudaGetSymbolAddress((void**)&xl, g_xl);
    cudaGetSymbolAddress((void**)&wh, g_Wh); cudaGetSymbolAddress((void**)&wl, g_Wl);

    int nx4 = NR * ND / 4, nw4 = ND * ND / 4;
    k_split<<<(nx4 + 255) / 256, 256>>>(x, xh, xl, nx4);
    k_split<<<(nw4 + 255) / 256, 256>>>(W, wh, wl, nw4);
    k_zero_rowsum<<<NR / 256, 256>>>();

    gemm_tc<0><<<dim3(ND / 128, NR / BM), 256, 98304>>>(b, nullptr);
    k_transpose<<<dim3(ND / 32, NR / 32), dim3(32, 8)>>>();
    gemm_tc<1><<<dim3(NR / 128, NR / BM), 256, 98304>>>(nullptr, nullptr);
    gemm_tc<2><<<dim3(ND / 256, NR / BM), 512, 98304>>>(nullptr, out);
}

// round 13
// speedup vs baseline: 1.5146x; 1.1763x over previous
#include <cuda_runtime.h>
#include <cuda_fp16.h>
#include <cstdint>
#include <math.h>

#define NR 8192
#define ND 1024
#define BM 128
#define BKD 32

// MODE 0 tile offsets within a stage (each [128][32] fp16 tile: 8192 B)
#define T_AHI 0
#define T_ALO 8192
#define T_BHI 16384
#define T_BLO 24576

// scratch
__device__ __half g_xh[(size_t)NR * ND], g_xl[(size_t)NR * ND];
__device__ __half g_Wh[(size_t)ND * ND], g_Wl[(size_t)ND * ND];
__device__ __half g_hh[(size_t)NR * ND];
__device__ __half g_hT[(size_t)ND * NR];
__device__ __half g_Pf[(size_t)NR * NR];
__device__ float g_rowsum[NR];

// ------------------------------------------------------------------ helpers
__device__ __forceinline__ uint32_t smem_u32(const void* p) {
    uint32_t a;
    asm("{ .reg .u64 t; cvta.to.shared.u64 t, %1; cvt.u32.u64 %0, t; }" : "=r"(a) : "l"(p));
    return a;
}
__device__ __forceinline__ void cp16(uint32_t s, const __half* g) {
    asm volatile("cp.async.cg.shared.global [%0], [%1], 16;"
                 :: "r"(s), "l"(__cvta_generic_to_global((const void*)g)) : "memory");
}
__device__ __forceinline__ void cp_commit() {
    asm volatile("cp.async.commit_group;" ::: "memory");
}
template <int N> __device__ __forceinline__ void cp_wait() {
    asm volatile("cp.async.wait_group %0;" :: "n"(N) : "memory");
}
__device__ __forceinline__ void ldsm4(uint32_t* r, uint32_t a) {
    asm volatile("ldmatrix.sync.aligned.m8n8.x4.shared.b16 {%0,%1,%2,%3}, [%4];"
                 : "=r"(r[0]), "=r"(r[1]), "=r"(r[2]), "=r"(r[3]) : "r"(a));
}
__device__ __forceinline__ void mma16816(float* c, const uint32_t* a, uint32_t b0, uint32_t b1) {
    asm volatile(
        "mma.sync.aligned.m16n8k16.row.col.f32.f16.f16.f32 "
        "{%0,%1,%2,%3},{%4,%5,%6,%7},{%8,%9},{%0,%1,%2,%3};"
        : "+f"(c[0]), "+f"(c[1]), "+f"(c[2]), "+f"(c[3])
        : "r"(a[0]), "r"(a[1]), "r"(a[2]), "r"(a[3]), "r"(b0), "r"(b1));
}
__device__ __forceinline__ float ftanh(float x) {
    float y; asm("tanh.approx.f32 %0, %1;" : "=f"(y) : "f"(x)); return y;
}
__device__ __forceinline__ void split16(float v, __half& h, __half& l) {
    h = __float2half_rn(v);
    l = __float2half_rn(v - __half2float(h));
}
// swizzled smem byte offset for (row, 16B-chunk) within a [rows][32] fp16 tile
__device__ __forceinline__ uint32_t swz(int row, int c) {
    return (uint32_t)(row * 64 + ((c ^ ((row >> 1) & 3)) << 4));
}

// load a [ITERS*THR/4 rows][32] fp16 tile
template <int THR, int ITERS>
__device__ __forceinline__ void load_tileT(const __half* __restrict__ base, size_t ld,
                                           int k0, uint32_t st, int tid) {
    #pragma unroll
    for (int i = 0; i < ITERS; i++) {
        int idx = tid + i * THR;
        int row = idx >> 2, c = idx & 3;
        cp16(st + swz(row, c), base + (size_t)row * ld + k0 + c * 8);
    }
}

// ------------------------------------------------------- GEMM (0=K1,1=K2,2=K3)
// MODE 0: 3 limb products (xhi*Whi + xhi*Wlo + xlo*Whi) — accurate h.
// MODE 1: 1 limb product h_hi * h_hi^T. Error calibrated from R12 measurement:
//         each dropped cross term adds ~0.9e-4 to output rel_err -> ~1.8e-4
//         total, 5x under tolerance. by<=bx blocks only; mirrors P and
//         accumulates row+col sums (tanh bounds scores: no max pass needed).
// MODE 2: single product (P @ h).
template <int MODE>
__global__ __launch_bounds__((MODE == 2) ? 512 : 256, (MODE == 2) ? 1 : 2)
void gemm_tc(const float* __restrict__ bias, float* __restrict__ out)
{
    constexpr int THR   = (MODE == 2) ? 512 : 256;
    constexpr int S     = (MODE == 2) ? 4 : 3;
    constexpr int STAGE = (MODE == 0) ? 32768 : (MODE == 1) ? 16384 : 24576;
    constexpr int BNx   = (MODE == 2) ? 256 : 128;
    constexpr int K     = (MODE == 2) ? NR : ND;
    constexpr int NC    = K / BKD;

    extern __shared__ char smem[];
    const uint32_t sb = smem_u32(smem);
    const int tid = threadIdx.x, lane = tid & 31, wid = tid >> 5;
    const int bx = blockIdx.x, by = blockIdx.y;
    if (MODE == 1 && by > bx) return;   // symmetry (uniform whole-CTA exit)
    const int mo = (wid & 3) * 32, no = (wid >> 2) * 64;

    const __half *Ahi, *Alo, *Bhi, *Blo;
    size_t lda, ldb;
    if (MODE == 0) {
        Ahi = g_xh + (size_t)by * BM * ND; Alo = g_xl + (size_t)by * BM * ND;
        Bhi = g_Wh + (size_t)bx * BNx * ND; Blo = g_Wl + (size_t)bx * BNx * ND;
        lda = ND; ldb = ND;
    } else if (MODE == 1) {
        Ahi = g_hh + (size_t)by * BM * ND; Alo = nullptr;
        Bhi = g_hh + (size_t)bx * BNx * ND; Blo = nullptr;
        lda = ND; ldb = ND;
    } else {
        Ahi = g_Pf + (size_t)by * BM * NR; Alo = nullptr;
        Bhi = g_hT + (size_t)bx * BNx * NR; Blo = nullptr;
        lda = NR; ldb = NR;
    }

    auto load_chunk = [&](int k0, uint32_t st) {
        if (MODE == 0) {
            load_tileT<THR, 2>(Ahi, lda, k0, st + T_AHI, tid);
            load_tileT<THR, 2>(Alo, lda, k0, st + T_ALO, tid);
            load_tileT<THR, 2>(Bhi, ldb, k0, st + T_BHI, tid);
            load_tileT<THR, 2>(Blo, ldb, k0, st + T_BLO, tid);
        } else if (MODE == 1) {
            load_tileT<THR, 2>(Ahi, lda, k0, st + 0, tid);      // 128x32
            load_tileT<THR, 2>(Bhi, ldb, k0, st + 8192, tid);   // 128x32
        } else {
            load_tileT<THR, 1>(Ahi, lda, k0, st + 0, tid);      // 128x32
            load_tileT<THR, 2>(Bhi, ldb, k0, st + 8192, tid);   // 256x32
        }
    };

    float c[2][8][4] = {};

    // prologue: chunks 0..S-2
    #pragma unroll
    for (int s = 0; s < S - 1; s++) {
        load_chunk(s * BKD, sb + s * STAGE);
        cp_commit();
    }

    for (int i = 0; i < NC; i++) {
        cp_wait<S - 2>();
        __syncthreads();

        if (i + S - 1 < NC)
            load_chunk((i + S - 1) * BKD, sb + ((i + S - 1) % S) * STAGE);
        cp_commit();

        const uint32_t st = sb + (i % S) * STAGE;
        #pragma unroll
        for (int ks = 0; ks < 2; ks++) {
            if (MODE == 0) {
                uint32_t ahi[2][4], bhi[4][4], tmp[4][4];
                #pragma unroll
                for (int mf = 0; mf < 2; mf++) {
                    int row = mo + mf * 16 + (lane & 15);
                    int ch = 2 * ks + (lane >> 4);
                    ldsm4(ahi[mf], st + T_AHI + swz(row, ch));
                }
                #pragma unroll
                for (int np = 0; np < 4; np++) {
                    int row = no + np * 16 + (lane & 7) + ((lane >> 4) << 3);
                    int ch = 2 * ks + ((lane >> 3) & 1);
                    ldsm4(bhi[np], st + T_BHI + swz(row, ch));
                }
                #pragma unroll
                for (int mf = 0; mf < 2; mf++)
                    #pragma unroll
                    for (int nf = 0; nf < 8; nf++)
                        mma16816(c[mf][nf], ahi[mf],
                                 bhi[nf >> 1][(nf & 1) * 2], bhi[nf >> 1][(nf & 1) * 2 + 1]);
                #pragma unroll
                for (int np = 0; np < 4; np++) {
                    int row = no + np * 16 + (lane & 7) + ((lane >> 4) << 3);
                    int ch = 2 * ks + ((lane >> 3) & 1);
                    ldsm4(tmp[np], st + T_BLO + swz(row, ch));
                }
                #pragma unroll
                for (int mf = 0; mf < 2; mf++)
                    #pragma unroll
                    for (int nf = 0; nf < 8; nf++)
                        mma16816(c[mf][nf], ahi[mf],
                                 tmp[nf >> 1][(nf & 1) * 2], tmp[nf >> 1][(nf & 1) * 2 + 1]);
                #pragma unroll
                for (int mf = 0; mf < 2; mf++) {
                    int row = mo + mf * 16 + (lane & 15);
                    int ch = 2 * ks + (lane >> 4);
                    ldsm4(tmp[mf], st + T_ALO + swz(row, ch));
                }
                #pragma unroll
                for (int mf = 0; mf < 2; mf++)
                    #pragma unroll
                    for (int nf = 0; nf < 8; nf++)
                        mma16816(c[mf][nf], tmp[mf],
                                 bhi[nf >> 1][(nf & 1) * 2], bhi[nf >> 1][(nf & 1) * 2 + 1]);
            } else {
                uint32_t a[2][4], b[4][4];
                #pragma unroll
                for (int mf = 0; mf < 2; mf++) {
                    int row = mo + mf * 16 + (lane & 15);
                    int ch = 2 * ks + (lane >> 4);
                    ldsm4(a[mf], st + swz(row, ch));
                }
                #pragma unroll
                for (int np = 0; np < 4; np++) {
                    int row = no + np * 16 + (lane & 7) + ((lane >> 4) << 3);
                    int ch = 2 * ks + ((lane >> 3) & 1);
                    ldsm4(b[np], st + 8192 + swz(row, ch));
                }
                #pragma unroll
                for (int mf = 0; mf < 2; mf++)
                    #pragma unroll
                    for (int nf = 0; nf < 8; nf++)
                        mma16816(c[mf][nf], a[mf],
                                 b[nf >> 1][(nf & 1) * 2], b[nf >> 1][(nf & 1) * 2 + 1]);
            }
        }
    }
    __syncthreads();   // all compute smem reads done (epilogue aliases stages)

    // --------------------------------------------------------- epilogue
    __half* sp = (__half*)smem;            // [128][132] staging (aliases stages)
    const bool mirror = (MODE == 1) && (bx != by);
    float rs[2][2] = {};
    #pragma unroll
    for (int mf = 0; mf < 2; mf++) {
        const int rl0 = mo + mf * 16 + (lane >> 2);
        const int rl1 = rl0 + 8;
        const int r0 = by * BM + rl0, r1 = by * BM + rl1;
        float inv0 = 0.f, inv1 = 0.f;
        if (MODE == 2) {
            inv0 = 1.0f / __ldg(&g_rowsum[r0]);
            inv1 = 1.0f / __ldg(&g_rowsum[r1]);
        }
        #pragma unroll
        for (int nf = 0; nf < 8; nf++) {
            const int cl = no + nf * 8 + 2 * (lane & 3);
            const int col = bx * BNx + cl;
            float v0 = c[mf][nf][0], v1 = c[mf][nf][1];
            float v2 = c[mf][nf][2], v3 = c[mf][nf][3];
            if (MODE == 0) {
                float b0 = __ldg(&bias[col]), b1 = __ldg(&bias[col + 1]);
                v0 += b0; v1 += b1; v2 += b0; v3 += b1;
                *(__half2*)(g_hh + (size_t)r0 * ND + col) =
                    __halves2half2(__float2half_rn(v0), __float2half_rn(v1));
                *(__half2*)(g_hh + (size_t)r1 * ND + col) =
                    __halves2half2(__float2half_rn(v2), __float2half_rn(v3));
            } else if (MODE == 1) {
                float p0 = __expf(ftanh(v0)), p1 = __expf(ftanh(v1));
                float p2 = __expf(ftanh(v2)), p3 = __expf(ftanh(v3));
                rs[mf][0] += p0 + p1; rs[mf][1] += p2 + p3;
                __half2 q0 = __halves2half2(__float2half_rn(p0), __float2half_rn(p1));
                __half2 q1 = __halves2half2(__float2half_rn(p2), __float2half_rn(p3));
                *(__half2*)(g_Pf + (size_t)r0 * NR + col) = q0;
                *(__half2*)(g_Pf + (size_t)r1 * NR + col) = q1;
                if (mirror) {
                    *(__half2*)(sp + rl0 * 132 + cl) = q0;
                    *(__half2*)(sp + rl1 * 132 + cl) = q1;
                }
            } else {
                float2 o0 = make_float2(tanhf(v0 * inv0), tanhf(v1 * inv0));
                float2 o1 = make_float2(tanhf(v2 * inv1), tanhf(v3 * inv1));
                *(float2*)(out + (size_t)r0 * ND + col) = o0;
                *(float2*)(out + (size_t)r1 * ND + col) = o1;
            }
        }
    }
    if (MODE == 1) {
        #pragma unroll
        for (int mf = 0; mf < 2; mf++)
            #pragma unroll
            for (int hh = 0; hh < 2; hh++) {
                float v = rs[mf][hh];
                v += __shfl_xor_sync(0xffffffffu, v, 1);
                v += __shfl_xor_sync(0xffffffffu, v, 2);
                if ((lane & 3) == 0) {
                    int r = by * BM + mo + mf * 16 + (lane >> 2) + hh * 8;
                    atomicAdd(&g_rowsum[r], v);
                }
            }
        if (mirror) {
            __syncthreads();
            // mirror block: write P[bx-range][by-range] coalesced + column sums
            const int cc = tid >> 1;            // local col 0..127
            const int rh = (tid & 1) * 64;      // row half
            float csum = 0.0f;
            #pragma unroll
            for (int q = 0; q < 8; q++) {
                __half tmp[8];
                #pragma unroll
                for (int r = 0; r < 8; r++) {
                    __half v = sp[(rh + q * 8 + r) * 132 + cc];
                    tmp[r] = v;
                    csum += __half2float(v);
                }
                *(uint4*)(g_Pf + (size_t)(bx * BNx + cc) * NR + by * BM + rh + q * 8) =
                    *(uint4*)tmp;
            }
            float o = __shfl_down_sync(0xffffffffu, csum, 1);
            if ((lane & 1) == 0) atomicAdd(&g_rowsum[bx * BNx + cc], csum + o);
        }
    }
}

// ------------------------------------------------------------- small kernels
__global__ void k_split(const float* __restrict__ src, __half* __restrict__ hi,
                        __half* __restrict__ lo, int n4)
{
    int i = blockIdx.x * blockDim.x + threadIdx.x;
    if (i >= n4) return;
    float4 v = ((const float4*)src)[i];
    __half h[4], l[4];
    split16(v.x, h[0], l[0]); split16(v.y, h[1], l[1]);
    split16(v.z, h[2], l[2]); split16(v.w, h[3], l[3]);
    ((uint2*)hi)[i] = *(uint2*)h;
    ((uint2*)lo)[i] = *(uint2*)l;
}
__global__ void k_zero_rowsum()
{
    int i = blockIdx.x * blockDim.x + threadIdx.x;
    if (i < NR) g_rowsum[i] = 0.0f;
}
// tiled transpose: g_hT[c][r] = g_hh[r][c]
__global__ void k_transpose()
{
    __shared__ __half t[32][33];
    int x = threadIdx.x, y = threadIdx.y;           // 32 x 8
    int r0 = blockIdx.y * 32, c0 = blockIdx.x * 32;
    #pragma unroll
    for (int i = 0; i < 32; i += 8)
        t[y + i][x] = g_hh[(size_t)(r0 + y + i) * ND + c0 + x];
    __syncthreads();
    #pragma unroll
    for (int i = 0; i < 32; i += 8)
        g_hT[(size_t)(c0 + y + i) * NR + r0 + x] = t[x][y + i];
}

// ------------------------------------------------------------------ launcher
extern "C" void kernel_launch(void* const* d_in, const int* in_sizes, int n_in,
                              void* d_out, int out_size)
{
    const float* x = (const float*)d_in[0];
    const float* W = (const float*)d_in[1];
    const float* b = (const float*)d_in[2];
    float* out = (float*)d_out;

    cudaFuncSetAttribute(gemm_tc<0>, cudaFuncAttributeMaxDynamicSharedMemorySize, 98304);
    cudaFuncSetAttribute(gemm_tc<1>, cudaFuncAttributeMaxDynamicSharedMemorySize, 49152);
    cudaFuncSetAttribute(gemm_tc<2>, cudaFuncAttributeMaxDynamicSharedMemorySize, 98304);

    __half *xh, *xl, *wh, *wl;
    cudaGetSymbolAddress((void**)&xh, g_xh); cudaGetSymbolAddress((void**)&xl, g_xl);
    cudaGetSymbolAddress((void**)&wh, g_Wh); cudaGetSymbolAddress((void**)&wl, g_Wl);

    int nx4 = NR * ND / 4, nw4 = ND * ND / 4;
    k_split<<<(nx4 + 255) / 256, 256>>>(x, xh, xl, nx4);
    k_split<<<(nw4 + 255) / 256, 256>>>(W, wh, wl, nw4);
    k_zero_rowsum<<<NR / 256, 256>>>();

    gemm_tc<0><<<dim3(ND / 128, NR / BM), 256, 98304>>>(b, nullptr);
    k_transpose<<<dim3(ND / 32, NR / 32), dim3(32, 8)>>>();
    gemm_tc<1><<<dim3(NR / 128, NR / BM), 256, 49152>>>(nullptr, nullptr);
    gemm_tc<2><<<dim3(ND / 256, NR / BM), 512, 98304>>>(nullptr, out);
}

// round 14
// speedup vs baseline: 1.7081x; 1.1278x over previous
#include <cuda_runtime.h>
#include <cuda_fp16.h>
#include <cstdint>
#include <math.h>

#define NR 8192
#define ND 1024
#define BM 128
#define BKD 32

// scratch (all fp16 single-limb now)
__device__ __half g_xh[(size_t)NR * ND];
__device__ __half g_Wh[(size_t)ND * ND];
__device__ __half g_hh[(size_t)NR * ND];
__device__ __half g_hT[(size_t)ND * NR];
__device__ __half g_Pf[(size_t)NR * NR];
__device__ float g_rowsum[NR];

// ------------------------------------------------------------------ helpers
__device__ __forceinline__ uint32_t smem_u32(const void* p) {
    uint32_t a;
    asm("{ .reg .u64 t; cvta.to.shared.u64 t, %1; cvt.u32.u64 %0, t; }" : "=r"(a) : "l"(p));
    return a;
}
__device__ __forceinline__ void cp16(uint32_t s, const __half* g) {
    asm volatile("cp.async.cg.shared.global [%0], [%1], 16;"
                 :: "r"(s), "l"(__cvta_generic_to_global((const void*)g)) : "memory");
}
__device__ __forceinline__ void cp_commit() {
    asm volatile("cp.async.commit_group;" ::: "memory");
}
template <int N> __device__ __forceinline__ void cp_wait() {
    asm volatile("cp.async.wait_group %0;" :: "n"(N) : "memory");
}
__device__ __forceinline__ void ldsm4(uint32_t* r, uint32_t a) {
    asm volatile("ldmatrix.sync.aligned.m8n8.x4.shared.b16 {%0,%1,%2,%3}, [%4];"
                 : "=r"(r[0]), "=r"(r[1]), "=r"(r[2]), "=r"(r[3]) : "r"(a));
}
__device__ __forceinline__ void mma16816(float* c, const uint32_t* a, uint32_t b0, uint32_t b1) {
    asm volatile(
        "mma.sync.aligned.m16n8k16.row.col.f32.f16.f16.f32 "
        "{%0,%1,%2,%3},{%4,%5,%6,%7},{%8,%9},{%0,%1,%2,%3};"
        : "+f"(c[0]), "+f"(c[1]), "+f"(c[2]), "+f"(c[3])
        : "r"(a[0]), "r"(a[1]), "r"(a[2]), "r"(a[3]), "r"(b0), "r"(b1));
}
__device__ __forceinline__ float ftanh(float x) {
    float y; asm("tanh.approx.f32 %0, %1;" : "=f"(y) : "f"(x)); return y;
}
// swizzled smem byte offset for (row, 16B-chunk) within a [rows][32] fp16 tile
__device__ __forceinline__ uint32_t swz(int row, int c) {
    return (uint32_t)(row * 64 + ((c ^ ((row >> 1) & 3)) << 4));
}

// load a [ITERS*THR/4 rows][32] fp16 tile
template <int THR, int ITERS>
__device__ __forceinline__ void load_tileT(const __half* __restrict__ base, size_t ld,
                                           int k0, uint32_t st, int tid) {
    #pragma unroll
    for (int i = 0; i < ITERS; i++) {
        int idx = tid + i * THR;
        int row = idx >> 2, c = idx & 3;
        cp16(st + swz(row, c), base + (size_t)row * ld + k0 + c * 8);
    }
}

// ------------------------------------------------------- GEMM (0=K1,1=K2,2=K3)
// All single-product fp16 GEMMs (error calibrated over R12/R13: each dropped
// limb cross-term adds ~1-2e-4 to output rel_err; total budget ~3e-4 << 1e-3).
// MODE 0: h = x_hi @ W_hi^T + b            -> fp16 h
// MODE 1: P = exp(tanh(h h^T)) upper-tri blocks only, mirrored; row+col sums
//         (tanh bounds scores so exp needs no max subtraction).
// MODE 2: out = tanh((P @ h) / rowsum)
template <int MODE>
__global__ __launch_bounds__((MODE == 2) ? 512 : 256, (MODE == 2) ? 1 : 2)
void gemm_tc(const float* __restrict__ bias, float* __restrict__ out)
{
    constexpr int THR   = (MODE == 2) ? 512 : 256;
    constexpr int S     = (MODE == 2) ? 4 : 3;
    constexpr int STAGE = (MODE == 2) ? 24576 : 16384;
    constexpr int BNx   = (MODE == 2) ? 256 : 128;
    constexpr int K     = (MODE == 2) ? NR : ND;
    constexpr int NC    = K / BKD;

    extern __shared__ char smem[];
    const uint32_t sb = smem_u32(smem);
    const int tid = threadIdx.x, lane = tid & 31, wid = tid >> 5;
    const int bx = blockIdx.x, by = blockIdx.y;
    if (MODE == 1 && by > bx) return;   // symmetry (uniform whole-CTA exit)
    const int mo = (wid & 3) * 32, no = (wid >> 2) * 64;

    const __half *Ag, *Bg;
    size_t lda, ldb;
    if (MODE == 0) {
        Ag = g_xh + (size_t)by * BM * ND;  Bg = g_Wh + (size_t)bx * BNx * ND;
        lda = ND; ldb = ND;
    } else if (MODE == 1) {
        Ag = g_hh + (size_t)by * BM * ND;  Bg = g_hh + (size_t)bx * BNx * ND;
        lda = ND; ldb = ND;
    } else {
        Ag = g_Pf + (size_t)by * BM * NR;  Bg = g_hT + (size_t)bx * BNx * NR;
        lda = NR; ldb = NR;
    }

    auto load_chunk = [&](int k0, uint32_t st) {
        if (MODE < 2) {
            load_tileT<THR, 2>(Ag, lda, k0, st + 0, tid);        // 128x32
            load_tileT<THR, 2>(Bg, ldb, k0, st + 8192, tid);     // 128x32
        } else {
            load_tileT<THR, 1>(Ag, lda, k0, st + 0, tid);        // 128x32
            load_tileT<THR, 2>(Bg, ldb, k0, st + 8192, tid);     // 256x32
        }
    };

    float c[2][8][4] = {};

    // prologue: chunks 0..S-2
    #pragma unroll
    for (int s = 0; s < S - 1; s++) {
        load_chunk(s * BKD, sb + s * STAGE);
        cp_commit();
    }

    for (int i = 0; i < NC; i++) {
        cp_wait<S - 2>();
        __syncthreads();

        if (i + S - 1 < NC)
            load_chunk((i + S - 1) * BKD, sb + ((i + S - 1) % S) * STAGE);
        cp_commit();

        const uint32_t st = sb + (i % S) * STAGE;
        #pragma unroll
        for (int ks = 0; ks < 2; ks++) {
            uint32_t a[2][4], b[4][4];
            #pragma unroll
            for (int mf = 0; mf < 2; mf++) {
                int row = mo + mf * 16 + (lane & 15);
                int ch = 2 * ks + (lane >> 4);
                ldsm4(a[mf], st + swz(row, ch));
            }
            #pragma unroll
            for (int np = 0; np < 4; np++) {
                int row = no + np * 16 + (lane & 7) + ((lane >> 4) << 3);
                int ch = 2 * ks + ((lane >> 3) & 1);
                ldsm4(b[np], st + 8192 + swz(row, ch));
            }
            #pragma unroll
            for (int mf = 0; mf < 2; mf++)
                #pragma unroll
                for (int nf = 0; nf < 8; nf++)
                    mma16816(c[mf][nf], a[mf],
                             b[nf >> 1][(nf & 1) * 2], b[nf >> 1][(nf & 1) * 2 + 1]);
        }
    }
    __syncthreads();   // all compute smem reads done (epilogue aliases stages)

    // --------------------------------------------------------- epilogue
    __half* sp = (__half*)smem;            // [128][132] staging (aliases stages)
    const bool mirror = (MODE == 1) && (bx != by);
    float rs[2][2] = {};
    #pragma unroll
    for (int mf = 0; mf < 2; mf++) {
        const int rl0 = mo + mf * 16 + (lane >> 2);
        const int rl1 = rl0 + 8;
        const int r0 = by * BM + rl0, r1 = by * BM + rl1;
        float inv0 = 0.f, inv1 = 0.f;
        if (MODE == 2) {
            inv0 = 1.0f / __ldg(&g_rowsum[r0]);
            inv1 = 1.0f / __ldg(&g_rowsum[r1]);
        }
        #pragma unroll
        for (int nf = 0; nf < 8; nf++) {
            const int cl = no + nf * 8 + 2 * (lane & 3);
            const int col = bx * BNx + cl;
            float v0 = c[mf][nf][0], v1 = c[mf][nf][1];
            float v2 = c[mf][nf][2], v3 = c[mf][nf][3];
            if (MODE == 0) {
                float b0 = __ldg(&bias[col]), b1 = __ldg(&bias[col + 1]);
                *(__half2*)(g_hh + (size_t)r0 * ND + col) =
                    __halves2half2(__float2half_rn(v0 + b0), __float2half_rn(v1 + b1));
                *(__half2*)(g_hh + (size_t)r1 * ND + col) =
                    __halves2half2(__float2half_rn(v2 + b0), __float2half_rn(v3 + b1));
            } else if (MODE == 1) {
                float p0 = __expf(ftanh(v0)), p1 = __expf(ftanh(v1));
                float p2 = __expf(ftanh(v2)), p3 = __expf(ftanh(v3));
                rs[mf][0] += p0 + p1; rs[mf][1] += p2 + p3;
                __half2 q0 = __halves2half2(__float2half_rn(p0), __float2half_rn(p1));
                __half2 q1 = __halves2half2(__float2half_rn(p2), __float2half_rn(p3));
                *(__half2*)(g_Pf + (size_t)r0 * NR + col) = q0;
                *(__half2*)(g_Pf + (size_t)r1 * NR + col) = q1;
                if (mirror) {
                    *(__half2*)(sp + rl0 * 132 + cl) = q0;
                    *(__half2*)(sp + rl1 * 132 + cl) = q1;
                }
            } else {
                float2 o0 = make_float2(tanhf(v0 * inv0), tanhf(v1 * inv0));
                float2 o1 = make_float2(tanhf(v2 * inv1), tanhf(v3 * inv1));
                *(float2*)(out + (size_t)r0 * ND + col) = o0;
                *(float2*)(out + (size_t)r1 * ND + col) = o1;
            }
        }
    }
    if (MODE == 1) {
        #pragma unroll
        for (int mf = 0; mf < 2; mf++)
            #pragma unroll
            for (int hh = 0; hh < 2; hh++) {
                float v = rs[mf][hh];
                v += __shfl_xor_sync(0xffffffffu, v, 1);
                v += __shfl_xor_sync(0xffffffffu, v, 2);
                if ((lane & 3) == 0) {
                    int r = by * BM + mo + mf * 16 + (lane >> 2) + hh * 8;
                    atomicAdd(&g_rowsum[r], v);
                }
            }
        if (mirror) {
            __syncthreads();
            // mirror block: write P[bx-range][by-range] coalesced + column sums
            const int cc = tid >> 1;            // local col 0..127
            const int rh = (tid & 1) * 64;      // row half
            float csum = 0.0f;
            #pragma unroll
            for (int q = 0; q < 8; q++) {
                __half tmp[8];
                #pragma unroll
                for (int r = 0; r < 8; r++) {
                    __half v = sp[(rh + q * 8 + r) * 132 + cc];
                    tmp[r] = v;
                    csum += __half2float(v);
                }
                *(uint4*)(g_Pf + (size_t)(bx * BNx + cc) * NR + by * BM + rh + q * 8) =
                    *(uint4*)tmp;
            }
            float o = __shfl_down_sync(0xffffffffu, csum, 1);
            if ((lane & 1) == 0) atomicAdd(&g_rowsum[bx * BNx + cc], csum + o);
        }
    }
}

// ------------------------------------------------------------- small kernels
__global__ void k_cast(const float* __restrict__ src, __half* __restrict__ dst, int n4)
{
    int i = blockIdx.x * blockDim.x + threadIdx.x;
    if (i >= n4) return;
    float4 v = ((const float4*)src)[i];
    __half h[4] = { __float2half_rn(v.x), __float2half_rn(v.y),
                    __float2half_rn(v.z), __float2half_rn(v.w) };
    ((uint2*)dst)[i] = *(uint2*)h;
}
__global__ void k_zero_rowsum()
{
    int i = blockIdx.x * blockDim.x + threadIdx.x;
    if (i < NR) g_rowsum[i] = 0.0f;
}
// tiled transpose: g_hT[c][r] = g_hh[r][c]
__global__ void k_transpose()
{
    __shared__ __half t[32][33];
    int x = threadIdx.x, y = threadIdx.y;           // 32 x 8
    int r0 = blockIdx.y * 32, c0 = blockIdx.x * 32;
    #pragma unroll
    for (int i = 0; i < 32; i += 8)
        t[y + i][x] = g_hh[(size_t)(r0 + y + i) * ND + c0 + x];
    __syncthreads();
    #pragma unroll
    for (int i = 0; i < 32; i += 8)
        g_hT[(size_t)(c0 + y + i) * NR + r0 + x] = t[x][y + i];
}

// ------------------------------------------------------------------ launcher
extern "C" void kernel_launch(void* const* d_in, const int* in_sizes, int n_in,
                              void* d_out, int out_size)
{
    const float* x = (const float*)d_in[0];
    const float* W = (const float*)d_in[1];
    const float* b = (const float*)d_in[2];
    float* out = (float*)d_out;

    cudaFuncSetAttribute(gemm_tc<0>, cudaFuncAttributeMaxDynamicSharedMemorySize, 49152);
    cudaFuncSetAttribute(gemm_tc<1>, cudaFuncAttributeMaxDynamicSharedMemorySize, 49152);
    cudaFuncSetAttribute(gemm_tc<2>, cudaFuncAttributeMaxDynamicSharedMemorySize, 98304);

    __half *xh, *wh;
    cudaGetSymbolAddress((void**)&xh, g_xh);
    cudaGetSymbolAddress((void**)&wh, g_Wh);

    int nx4 = NR * ND / 4, nw4 = ND * ND / 4;
    k_cast<<<(nx4 + 255) / 256, 256>>>(x, xh, nx4);
    k_cast<<<(nw4 + 255) / 256, 256>>>(W, wh, nw4);
    k_zero_rowsum<<<NR / 256, 256>>>();

    gemm_tc<0><<<dim3(ND / 128, NR / BM), 256, 49152>>>(b, nullptr);
    k_transpose<<<dim3(ND / 32, NR / 32), dim3(32, 8)>>>();
    gemm_tc<1><<<dim3(NR / 128, NR / BM), 256, 49152>>>(nullptr, nullptr);
    gemm_tc<2><<<dim3(ND / 256, NR / BM), 512, 98304>>>(nullptr, out);
}